// round 3
// baseline (speedup 1.0000x reference)
#include <cuda_runtime.h>

#define B_DIM 4
#define T_DIM 1024
#define VD    512
#define HALF  256
#define NL    64
#define C_DIM 256

// Scratch accumulator A[b][l][d] : 4*64*256 floats = 256 KB (L2-resident).
// No zero-init needed: every cell is written exactly once by its owner block.
__device__ float g_A[B_DIM * NL * HALF];

// ---------------------------------------------------------------------------
// Kernel 1: gather + per-label accumulate, ownership model (no atomics).
//   Block (b, l) computes A[b, l, d] = sum_{t: label[b,t]=l} scores[b,t] *
//                                      weight[indices[b,t], off+d]
// Grid: B_DIM*NL = 256 blocks, 256 threads (thread = d).
// Blocks 0..3 additionally zero `out` (K2 runs after K1, so this is safe).
// ---------------------------------------------------------------------------
__global__ void vb_gather_kernel(const int*   __restrict__ indices,
                                 const float* __restrict__ scores,
                                 const int*   __restrict__ label,
                                 const int*   __restrict__ index_sel,
                                 const float* __restrict__ weight,
                                 float*       __restrict__ out) {
    // Worst case: every token of this batch row has this label.
    __shared__ int   s_idx[T_DIM];
    __shared__ float s_sc [T_DIM];
    __shared__ int   s_cnt;

    const int tid = threadIdx.x;
    const int b   = blockIdx.x / NL;
    const int l   = blockIdx.x % NL;

    if (blockIdx.x < B_DIM) out[blockIdx.x * C_DIM + tid] = 0.0f;
    if (tid == 0) s_cnt = 0;
    __syncthreads();

    // Scan this batch row's labels, compact matches.
    #pragma unroll
    for (int j = 0; j < T_DIM / 256; j++) {
        int t = b * T_DIM + j * 256 + tid;
        if (label[t] == l) {
            int pos = atomicAdd(&s_cnt, 1);
            s_idx[pos] = indices[t];
            s_sc [pos] = scores[t];
        }
    }
    __syncthreads();

    const int cnt = s_cnt;
    const int off = (index_sel[0] == 1) ? HALF : 0;
    const int d   = tid;

    float acc = 0.0f;
    int j = 0;
    // 4-way unroll for memory-level parallelism on the gathered rows.
    for (; j + 4 <= cnt; j += 4) {
        float v0 = weight[s_idx[j + 0] * VD + off + d];
        float v1 = weight[s_idx[j + 1] * VD + off + d];
        float v2 = weight[s_idx[j + 2] * VD + off + d];
        float v3 = weight[s_idx[j + 3] * VD + off + d];
        acc += v0 * s_sc[j + 0] + v1 * s_sc[j + 1]
             + v2 * s_sc[j + 2] + v3 * s_sc[j + 3];
    }
    for (; j < cnt; j++)
        acc += weight[s_idx[j] * VD + off + d] * s_sc[j];

    g_A[(b * NL + l) * HALF + d] = acc;   // exclusive write, no atomic
}

// ---------------------------------------------------------------------------
// Kernel 2: reduction GEMM
//   out[b,c] += sum_{d in chunk} A[b, l, d] * W[l, off+d, c]
// Grid: NL * (HALF/DCHUNK) = 256 blocks; 256 threads (thread = c).
// ---------------------------------------------------------------------------
#define DCHUNK 64

__global__ void vb_gemm_kernel(const float* __restrict__ W,
                               const int*   __restrict__ index_sel,
                               float*       __restrict__ out) {
    const int l  = blockIdx.x / (HALF / DCHUNK);
    const int dc = blockIdx.x % (HALF / DCHUNK);
    const int d0 = dc * DCHUNK;
    const int c  = threadIdx.x;

    const int off = (index_sel[0] == 1) ? HALF : 0;

    __shared__ float sA[B_DIM][DCHUNK];
    {
        int b  = threadIdx.x / DCHUNK;
        int dd = threadIdx.x % DCHUNK;
        sA[b][dd] = g_A[(b * NL + l) * HALF + d0 + dd];
    }
    __syncthreads();

    float acc0 = 0.f, acc1 = 0.f, acc2 = 0.f, acc3 = 0.f;
    const float* Wp = W + ((l * VD) + off + d0) * C_DIM + c;

    #pragma unroll 8
    for (int d = 0; d < DCHUNK; d++) {
        float w = Wp[d * C_DIM];           // coalesced across threads (c)
        acc0 += sA[0][d] * w;
        acc1 += sA[1][d] * w;
        acc2 += sA[2][d] * w;
        acc3 += sA[3][d] * w;
    }

    atomicAdd(&out[0 * C_DIM + c], acc0);
    atomicAdd(&out[1 * C_DIM + c], acc1);
    atomicAdd(&out[2 * C_DIM + c], acc2);
    atomicAdd(&out[3 * C_DIM + c], acc3);
}

// ---------------------------------------------------------------------------
// Launch
// Inputs (metadata order): indices(int32 B*T), scores(f32 B*T),
//   W(f32 64*512*256), label(int32 B*T), index(int32 scalar),
//   weight(f32 262144*512). Output: f32 B*C = 1024.
// ---------------------------------------------------------------------------
extern "C" void kernel_launch(void* const* d_in, const int* in_sizes, int n_in,
                              void* d_out, int out_size) {
    const int*   indices   = (const int*)  d_in[0];
    const float* scores    = (const float*)d_in[1];
    const float* W         = (const float*)d_in[2];
    const int*   label     = (const int*)  d_in[3];
    const int*   index_sel = (const int*)  d_in[4];
    const float* weight    = (const float*)d_in[5];
    float*       out       = (float*)d_out;

    vb_gather_kernel<<<B_DIM * NL, 256>>>(indices, scores, label, index_sel,
                                          weight, out);
    vb_gemm_kernel<<<NL * (HALF / DCHUNK), 256>>>(W, index_sel, out);
}